// round 13
// baseline (speedup 1.0000x reference)
#include <cuda_runtime.h>
#include <cuda_fp16.h>
#include <cstdint>

#define B_  128
#define T_  512
#define C_  384
#define NH_ 6
#define HD_ 64

// ---------------- scratch (device globals: allocation-free) ----------------
__device__ __half g_xh[(size_t)B_ * T_ * C_];
__device__ __half g_wqkvh[(size_t)3 * C_ * C_];
__device__ __half g_wouth[(size_t)C_ * C_];
__device__ __half g_qh[(size_t)B_ * NH_ * T_ * HD_];
__device__ __half g_kh[(size_t)B_ * NH_ * T_ * HD_];
__device__ __half g_vh[(size_t)B_ * NH_ * T_ * HD_];
__device__ __half g_oh[(size_t)B_ * T_ * C_];

// ---------------- low-level helpers ----------------
__device__ __forceinline__ void cp_async16(void* smem, const void* gmem) {
    unsigned s = (unsigned)__cvta_generic_to_shared(smem);
    asm volatile("cp.async.cg.shared.global [%0], [%1], 16;\n" :: "r"(s), "l"(gmem));
}
__device__ __forceinline__ void cp_commit() {
    asm volatile("cp.async.commit_group;\n");
}
template <int N>
__device__ __forceinline__ void cp_wait() {
    asm volatile("cp.async.wait_group %0;\n" :: "n"(N));
}
__device__ __forceinline__ unsigned smem_u32(const void* p) {
    return (unsigned)__cvta_generic_to_shared(p);
}
__device__ __forceinline__ void ldsm_x4(unsigned& r0, unsigned& r1,
                                        unsigned& r2, unsigned& r3, unsigned a) {
    asm volatile("ldmatrix.sync.aligned.m8n8.x4.shared.b16 {%0,%1,%2,%3}, [%4];"
                 : "=r"(r0), "=r"(r1), "=r"(r2), "=r"(r3) : "r"(a));
}
__device__ __forceinline__ void ldsm_x4_t(unsigned& r0, unsigned& r1,
                                          unsigned& r2, unsigned& r3, unsigned a) {
    asm volatile("ldmatrix.sync.aligned.m8n8.x4.trans.shared.b16 {%0,%1,%2,%3}, [%4];"
                 : "=r"(r0), "=r"(r1), "=r"(r2), "=r"(r3) : "r"(a));
}
__device__ __forceinline__ void mma_f16(unsigned& d0, unsigned& d1,
                                        unsigned a0, unsigned a1, unsigned a2,
                                        unsigned a3, unsigned b0, unsigned b1) {
    asm volatile(
        "mma.sync.aligned.m16n8k16.row.col.f16.f16.f16.f16 "
        "{%0,%1},{%2,%3,%4,%5},{%6,%7},{%0,%1};"
        : "+r"(d0), "+r"(d1)
        : "r"(a0), "r"(a1), "r"(a2), "r"(a3), "r"(b0), "r"(b1));
}
__device__ __forceinline__ void mma_f32(float& c0, float& c1, float& c2, float& c3,
                                        unsigned a0, unsigned a1, unsigned a2,
                                        unsigned a3, unsigned b0, unsigned b1) {
    asm volatile(
        "mma.sync.aligned.m16n8k16.row.col.f32.f16.f16.f32 "
        "{%0,%1,%2,%3},{%4,%5,%6,%7},{%8,%9},{%0,%1,%2,%3};"
        : "+f"(c0), "+f"(c1), "+f"(c2), "+f"(c3)
        : "r"(a0), "r"(a1), "r"(a2), "r"(a3), "r"(b0), "r"(b1));
}

// ---------------------------------------------------------------------------
// fp32 -> fp16 converter (vectorized, n multiple of 2048)
// ---------------------------------------------------------------------------
__global__ void cvt_f2h(const float* __restrict__ in, __half* __restrict__ out) {
    size_t i = ((size_t)blockIdx.x * blockDim.x + threadIdx.x) * 8;
    float4 a = *(const float4*)(in + i);
    float4 b = *(const float4*)(in + i + 4);
    __half2 h0 = __floats2half2_rn(a.x, a.y);
    __half2 h1 = __floats2half2_rn(a.z, a.w);
    __half2 h2 = __floats2half2_rn(b.x, b.y);
    __half2 h3 = __floats2half2_rn(b.z, b.w);
    uint4 pack;
    pack.x = *(unsigned*)&h0; pack.y = *(unsigned*)&h1;
    pack.z = *(unsigned*)&h2; pack.w = *(unsigned*)&h3;
    *(uint4*)(out + i) = pack;
}

// ===========================================================================
// Raw-mma fp16 GEMM (NT), 3-stage cp.async pipeline:
// BM=128, BN=128, BK=64, 8 warps, warp tile 32x64 (2 m16 x 8 n8).
// One __syncthreads per K-iteration; wait_group(1) keeps one prefetch in
// flight. EPI=0: fp32 store. EPI=1: register RoPE epilogue.
// ===========================================================================
#define LDR 72
#define STAGE_HALF (128 * LDR)
#define NSTAGE 3
#define GEMM_SMEM_R (NSTAGE * 2 * STAGE_HALF * 2)   // 110592 B

template <int EPI>
__global__ void __launch_bounds__(256) gemm_r(
    const __half* __restrict__ A, const __half* __restrict__ Bw,
    float* __restrict__ Cc,
    const float* __restrict__ cosb, const float* __restrict__ sinb,
    __half* __restrict__ qo, __half* __restrict__ ko, __half* __restrict__ vo,
    int M, int N, int K)
{
    extern __shared__ char smem[];
    __half* sS = (__half*)smem;   // [NSTAGE][ A(128xLDR) | B(128xLDR) ]

    const int tid = threadIdx.x;
    const int w   = tid >> 5;
    const int l   = tid & 31;
    const int bm  = blockIdx.y * 128;
    const int bn  = blockIdx.x * 128;
    const int m_off = (w >> 1) * 32;
    const int n_off = (w & 1) * 64;

    const unsigned uS = smem_u32(sS);
    const int lrow16 = (l & 7) + ((l >> 3) & 1) * 8;
    const int lcol8  = (l >> 4) * 8;
    const int g   = l >> 2;
    const int t4  = l & 3;

    float c[2][8][4];
    #pragma unroll
    for (int i = 0; i < 2; i++)
        #pragma unroll
        for (int j = 0; j < 8; j++)
            #pragma unroll
            for (int e = 0; e < 4; e++) c[i][j][e] = 0.0f;

    auto load_stage = [&](int k0, int st) {
        __half* dA = sS + st * 2 * STAGE_HALF;
        __half* dB = dA + STAGE_HALF;
        #pragma unroll
        for (int p = 0; p < 4; p++) {
            int cidx = p * 256 + tid;
            int r = cidx >> 3, c8 = (cidx & 7) * 8;
            cp_async16(&dA[r * LDR + c8], &A[(size_t)(bm + r) * K + k0 + c8]);
        }
        #pragma unroll
        for (int p = 0; p < 4; p++) {
            int cidx = p * 256 + tid;
            int r = cidx >> 3, c8 = (cidx & 7) * 8;
            cp_async16(&dB[r * LDR + c8], &Bw[(size_t)(bn + r) * K + k0 + c8]);
        }
        cp_commit();
    };

    const int nk = K / 64;            // 6
    load_stage(0, 0);
    if (nk > 1) load_stage(64, 1);

    int st = 0;
    for (int ki = 0; ki < nk; ki++) {
        if (ki + 1 < nk) cp_wait<1>(); else cp_wait<0>();
        __syncthreads();
        if (ki + 2 < nk) load_stage((ki + 2) * 64, (ki + 2) % NSTAGE);

        const unsigned baseA = uS + (unsigned)(st * 2 * STAGE_HALF * 2);
        const unsigned baseB = baseA + (unsigned)(STAGE_HALF * 2);
        st = (st + 1 == NSTAGE) ? 0 : st + 1;

        #pragma unroll
        for (int kp = 0; kp < 2; kp++) {
            unsigned bB[8][4];
            #pragma unroll
            for (int j = 0; j < 8; j++) {
                unsigned addr = baseB +
                    (unsigned)(((n_off + 8 * j + (l & 7)) * LDR +
                                kp * 32 + (l >> 3) * 8) * 2);
                ldsm_x4(bB[j][0], bB[j][1], bB[j][2], bB[j][3], addr);
            }
            #pragma unroll
            for (int kc = 0; kc < 2; kc++) {
                unsigned aA[2][4];
                #pragma unroll
                for (int i = 0; i < 2; i++) {
                    unsigned addr = baseA +
                        (unsigned)(((m_off + 16 * i + lrow16) * LDR +
                                    kp * 32 + kc * 16 + lcol8) * 2);
                    ldsm_x4(aA[i][0], aA[i][1], aA[i][2], aA[i][3], addr);
                }
                #pragma unroll
                for (int i = 0; i < 2; i++)
                    #pragma unroll
                    for (int j = 0; j < 8; j++)
                        mma_f32(c[i][j][0], c[i][j][1], c[i][j][2], c[i][j][3],
                                aA[i][0], aA[i][1], aA[i][2], aA[i][3],
                                bB[j][2 * kc], bB[j][2 * kc + 1]);
            }
        }
    }

    if (EPI == 0) {
        #pragma unroll
        for (int i = 0; i < 2; i++) {
            size_t row_lo = (size_t)(bm + m_off + 16 * i + g);
            size_t row_hi = row_lo + 8;
            float* plo = Cc + row_lo * N + bn + n_off + 2 * t4;
            float* phi = Cc + row_hi * N + bn + n_off + 2 * t4;
            #pragma unroll
            for (int j = 0; j < 8; j++) {
                *(float2*)(plo + 8 * j) = make_float2(c[i][j][0], c[i][j][1]);
                *(float2*)(phi + 8 * j) = make_float2(c[i][j][2], c[i][j][3]);
            }
        }
    } else {
        const int gidx = 2 * blockIdx.x + (w & 1);   // 0..17
        const int i3 = gidx / NH_;
        const int hh = gidx - NH_ * i3;
        const float sc = (i3 == 0) ? 0.125f : 1.0f;
        __half* dst0 = (i3 == 0 ? qo : (i3 == 1 ? ko : vo));
        const int d0 = 2 * t4;

        #pragma unroll
        for (int i = 0; i < 2; i++) {
            #pragma unroll
            for (int rh = 0; rh < 2; rh++) {
                int gm = bm + m_off + 16 * i + g + 8 * rh;
                int b  = gm >> 9, t = gm & 511;
                int e0 = 2 * rh, e1 = 2 * rh + 1;
                float v[8][2];
                #pragma unroll
                for (int j = 0; j < 8; j++) {
                    v[j][0] = c[i][j][e0];
                    v[j][1] = c[i][j][e1];
                }
                if (i3 < 2) {
                    float cs0 = cosb[t * 8 + d0], cs1 = cosb[t * 8 + d0 + 1];
                    float sn0 = sinb[t * 8 + d0], sn1 = sinb[t * 8 + d0 + 1];
                    float r00 = v[0][0] * cs0 - v[1][0] * sn0;
                    float r01 = v[0][1] * cs1 - v[1][1] * sn1;
                    float r10 = v[1][0] * cs0 + v[0][0] * sn0;
                    float r11 = v[1][1] * cs1 + v[0][1] * sn1;
                    v[0][0] = r00; v[0][1] = r01;
                    v[1][0] = r10; v[1][1] = r11;
                }
                __half* dst = dst0 + (((size_t)b * NH_ + hh) * T_ + t) * HD_ + d0;
                #pragma unroll
                for (int j = 0; j < 8; j++) {
                    __half2 h = __floats2half2_rn(v[j][0] * sc, v[j][1] * sc);
                    *(__half2*)(dst + 8 * j) = h;
                }
            }
        }
    }
}

// ===========================================================================
// Attention v6 (R11, unchanged): FA2-style register-resident P.
// ===========================================================================
#define AQ_BYTES  (128 * 72 * 2)
#define AKV_HALF  (64 * 72)
#define ATTN_SMEM (AQ_BYTES + 4 * AKV_HALF * 2)   // 55296

__global__ void __launch_bounds__(256, 2) attn_kernel(
    const __half* __restrict__ q, const __half* __restrict__ k,
    const __half* __restrict__ v, __half* __restrict__ o)
{
    extern __shared__ char smem[];
    __half* sQp = (__half*)smem;
    __half* sKp = (__half*)(smem + AQ_BYTES);
    __half* sVp = (__half*)(smem + AQ_BYTES + 2 * AKV_HALF * 2);

    const int qt = blockIdx.x;
    const int h  = blockIdx.y, b = blockIdx.z;
    const int tid = threadIdx.x, w = tid >> 5, l = tid & 31;
    const int nkt = 2 * (qt + 1);

    const __half* qbase = q + (((size_t)b * NH_ + h) * T_ + qt * 128) * HD_;
    const __half* kbase = k + (((size_t)b * NH_ + h) * T_) * HD_;
    const __half* vbase = v + (((size_t)b * NH_ + h) * T_) * HD_;

    #pragma unroll
    for (int p = 0; p < 4; p++) {
        int idx = p * 256 + tid;
        int r = idx >> 3, c8 = (idx & 7) * 8;
        cp_async16(&sQp[r * 72 + c8], &qbase[r * 64 + c8]);
    }
    #pragma unroll
    for (int p = 0; p < 2; p++) {
        int idx = p * 256 + tid;
        int r = idx >> 3, c8 = (idx & 7) * 8;
        cp_async16(&sKp[r * 72 + c8], &kbase[r * 64 + c8]);
        cp_async16(&sVp[r * 72 + c8], &vbase[r * 64 + c8]);
    }
    cp_commit();
    cp_wait<0>();
    __syncthreads();

    const unsigned uQ = smem_u32(sQp);
    const unsigned uK = smem_u32(sKp);
    const unsigned uV = smem_u32(sVp);

    const int qrow0 = w * 16;
    const int lrow  = (l & 7) + ((l >> 3) & 1) * 8;
    const int lcol8 = (l >> 4) * 8;
    const int g  = l >> 2;
    const int t4 = l & 3;

    unsigned aQ[4][4];
    #pragma unroll
    for (int kk = 0; kk < 4; kk++) {
        unsigned addr = uQ + (unsigned)(((qrow0 + lrow) * 72 + kk * 16 + lcol8) * 2);
        ldsm_x4(aQ[kk][0], aQ[kk][1], aQ[kk][2], aQ[kk][3], addr);
    }

    float oacc[8][4];
    #pragma unroll
    for (int j = 0; j < 8; j++)
        #pragma unroll
        for (int e = 0; e < 4; e++) oacc[j][e] = 0.0f;
    float rs_lo = 0.0f, rs_hi = 0.0f;

    const int qw_base = qt * 128 + qrow0;
    const int grow_lo = qw_base + g;
    const int grow_hi = grow_lo + 8;

    for (int kt = 0; kt < nkt; kt++) {
        const unsigned curK = uK + (unsigned)((kt & 1) * AKV_HALF * 2);
        const unsigned curV = uV + (unsigned)((kt & 1) * AKV_HALF * 2);

        if (kt + 1 < nkt) {
            const __half* kn = kbase + (size_t)(kt + 1) * 64 * 64;
            const __half* vn = vbase + (size_t)(kt + 1) * 64 * 64;
            __half* dK = sKp + ((kt + 1) & 1) * AKV_HALF;
            __half* dV = sVp + ((kt + 1) & 1) * AKV_HALF;
            #pragma unroll
            for (int p = 0; p < 2; p++) {
                int idx = p * 256 + tid;
                int r = idx >> 3, c8 = (idx & 7) * 8;
                cp_async16(&dK[r * 72 + c8], &kn[r * 64 + c8]);
                cp_async16(&dV[r * 72 + c8], &vn[r * 64 + c8]);
            }
            cp_commit();
        }

        const bool active = (64 * kt <= qw_base + 15);
        if (active) {
            const bool maskt = (64 * kt + 63 > qw_base);
            unsigned P[8][2];

            #pragma unroll
            for (int j = 0; j < 8; j++) {
                unsigned d0 = 0, d1 = 0;
                #pragma unroll
                for (int kp = 0; kp < 2; kp++) {
                    unsigned b0, b1, b2, b3;
                    unsigned addr = curK +
                        (unsigned)(((8 * j + (l & 7)) * 72 + kp * 32 + (l >> 3) * 8) * 2);
                    ldsm_x4(b0, b1, b2, b3, addr);
                    mma_f16(d0, d1, aQ[2 * kp][0], aQ[2 * kp][1],
                            aQ[2 * kp][2], aQ[2 * kp][3], b0, b1);
                    mma_f16(d0, d1, aQ[2 * kp + 1][0], aQ[2 * kp + 1][1],
                            aQ[2 * kp + 1][2], aQ[2 * kp + 1][3], b2, b3);
                }
                float2 f0 = __half22float2(*(__half2*)&d0);
                float2 f1 = __half22float2(*(__half2*)&d1);
                float e00 = __expf(f0.x), e01 = __expf(f0.y);
                float e10 = __expf(f1.x), e11 = __expf(f1.y);
                if (maskt) {
                    int c0 = kt * 64 + 8 * j + 2 * t4;
                    if (c0     > grow_lo) e00 = 0.0f;
                    if (c0 + 1 > grow_lo) e01 = 0.0f;
                    if (c0     > grow_hi) e10 = 0.0f;
                    if (c0 + 1 > grow_hi) e11 = 0.0f;
                }
                rs_lo += e00 + e01;
                rs_hi += e10 + e11;
                __half2 p0 = __floats2half2_rn(e00, e01);
                __half2 p1 = __floats2half2_rn(e10, e11);
                P[j][0] = *(unsigned*)&p0;
                P[j][1] = *(unsigned*)&p1;
            }

            #pragma unroll
            for (int kk = 0; kk < 4; kk++) {
                unsigned pa0 = P[2 * kk][0],     pa1 = P[2 * kk][1];
                unsigned pa2 = P[2 * kk + 1][0], pa3 = P[2 * kk + 1][1];
                #pragma unroll
                for (int j2 = 0; j2 < 4; j2++) {
                    unsigned m0, m1, m2, m3;
                    unsigned addr = curV +
                        (unsigned)(((16 * kk + lrow) * 72 + j2 * 16 + lcol8) * 2);
                    ldsm_x4_t(m0, m1, m2, m3, addr);
                    mma_f32(oacc[2 * j2][0], oacc[2 * j2][1],
                            oacc[2 * j2][2], oacc[2 * j2][3],
                            pa0, pa1, pa2, pa3, m0, m1);
                    mma_f32(oacc[2 * j2 + 1][0], oacc[2 * j2 + 1][1],
                            oacc[2 * j2 + 1][2], oacc[2 * j2 + 1][3],
                            pa0, pa1, pa2, pa3, m2, m3);
                }
            }
        }

        cp_wait<0>();
        __syncthreads();
    }

    rs_lo += __shfl_xor_sync(0xffffffffu, rs_lo, 1);
    rs_lo += __shfl_xor_sync(0xffffffffu, rs_lo, 2);
    rs_hi += __shfl_xor_sync(0xffffffffu, rs_hi, 1);
    rs_hi += __shfl_xor_sync(0xffffffffu, rs_hi, 2);
    const float inv_lo = 1.0f / rs_lo;
    const float inv_hi = 1.0f / rs_hi;

    const size_t row_lo = (size_t)b * T_ + qt * 128 + qrow0 + g;
    const size_t row_hi = row_lo + 8;
    __half* obase_lo = o + row_lo * C_ + h * HD_;
    __half* obase_hi = o + row_hi * C_ + h * HD_;
    #pragma unroll
    for (int j = 0; j < 8; j++) {
        int col = 8 * j + 2 * t4;
        __half2 lo = __floats2half2_rn(oacc[j][0] * inv_lo, oacc[j][1] * inv_lo);
        __half2 hi = __floats2half2_rn(oacc[j][2] * inv_hi, oacc[j][3] * inv_hi);
        *(__half2*)(obase_lo + col) = lo;
        *(__half2*)(obase_hi + col) = hi;
    }
}

// ---------------------------------------------------------------------------
extern "C" void kernel_launch(void* const* d_in, const int* in_sizes, int n_in,
                              void* d_out, int out_size)
{
    const float* x    = (const float*)d_in[0];
    const float* Wqkv = (const float*)d_in[1];
    const float* Wout = (const float*)d_in[2];
    const float* cosb = (const float*)d_in[3];
    const float* sinb = (const float*)d_in[4];
    float* out = (float*)d_out;

    __half *xh, *wqkvh, *wouth, *qh, *kh, *vh, *oh;
    cudaGetSymbolAddress((void**)&xh,    g_xh);
    cudaGetSymbolAddress((void**)&wqkvh, g_wqkvh);
    cudaGetSymbolAddress((void**)&wouth, g_wouth);
    cudaGetSymbolAddress((void**)&qh,    g_qh);
    cudaGetSymbolAddress((void**)&kh,    g_kh);
    cudaGetSymbolAddress((void**)&vh,    g_vh);
    cudaGetSymbolAddress((void**)&oh,    g_oh);

    const int M = B_ * T_;

    cudaFuncSetAttribute(gemm_r<0>,
                         cudaFuncAttributeMaxDynamicSharedMemorySize, GEMM_SMEM_R);
    cudaFuncSetAttribute(gemm_r<1>,
                         cudaFuncAttributeMaxDynamicSharedMemorySize, GEMM_SMEM_R);
    cudaFuncSetAttribute(attn_kernel,
                         cudaFuncAttributeMaxDynamicSharedMemorySize, ATTN_SMEM);

    cvt_f2h<<<(B_ * T_ * C_) / 2048, 256>>>(x, xh);
    cvt_f2h<<<(3 * C_ * C_) / 2048, 256>>>(Wqkv, wqkvh);
    cvt_f2h<<<(C_ * C_) / 2048, 256>>>(Wout, wouth);

    // K1: qkv GEMM (raw mma, 3-stage pipeline) + register RoPE epilogue
    {
        dim3 grid((3 * C_) / 128, M / 128);
        gemm_r<1><<<grid, 256, GEMM_SMEM_R>>>(
            xh, wqkvh, nullptr, cosb, sinb, qh, kh, vh, M, 3 * C_, C_);
    }
    // K2: causal attention (FA2-style)
    {
        dim3 grid(T_ / 128, NH_, B_);
        attn_kernel<<<grid, 256, ATTN_SMEM>>>(qh, kh, vh, oh);
    }
    // K3: out = o @ Wout^T
    {
        dim3 grid(C_ / 128, M / 128);
        gemm_r<0><<<grid, 256, GEMM_SMEM_R>>>(
            oh, wouth, out, nullptr, nullptr, nullptr, nullptr, nullptr,
            M, C_, C_);
    }
}

// round 14
// speedup vs baseline: 1.1163x; 1.1163x over previous
#include <cuda_runtime.h>
#include <cuda_fp16.h>
#include <cstdint>

#define B_  128
#define T_  512
#define C_  384
#define NH_ 6
#define HD_ 64

// ---------------- scratch (device globals: allocation-free) ----------------
__device__ __half g_xh[(size_t)B_ * T_ * C_];
__device__ __half g_wqkvh[(size_t)3 * C_ * C_];
__device__ __half g_wouth[(size_t)C_ * C_];
__device__ __half g_qh[(size_t)B_ * NH_ * T_ * HD_];
__device__ __half g_kh[(size_t)B_ * NH_ * T_ * HD_];
__device__ __half g_vh[(size_t)B_ * NH_ * T_ * HD_];
__device__ __half g_oh[(size_t)B_ * T_ * C_];

// ---------------- low-level helpers ----------------
__device__ __forceinline__ void cp_async16(void* smem, const void* gmem) {
    unsigned s = (unsigned)__cvta_generic_to_shared(smem);
    asm volatile("cp.async.cg.shared.global [%0], [%1], 16;\n" :: "r"(s), "l"(gmem));
}
__device__ __forceinline__ void cp_commit() {
    asm volatile("cp.async.commit_group;\n");
}
template <int N>
__device__ __forceinline__ void cp_wait() {
    asm volatile("cp.async.wait_group %0;\n" :: "n"(N));
}
__device__ __forceinline__ unsigned smem_u32(const void* p) {
    return (unsigned)__cvta_generic_to_shared(p);
}
__device__ __forceinline__ void ldsm_x4(unsigned& r0, unsigned& r1,
                                        unsigned& r2, unsigned& r3, unsigned a) {
    asm volatile("ldmatrix.sync.aligned.m8n8.x4.shared.b16 {%0,%1,%2,%3}, [%4];"
                 : "=r"(r0), "=r"(r1), "=r"(r2), "=r"(r3) : "r"(a));
}
__device__ __forceinline__ void ldsm_x4_t(unsigned& r0, unsigned& r1,
                                          unsigned& r2, unsigned& r3, unsigned a) {
    asm volatile("ldmatrix.sync.aligned.m8n8.x4.trans.shared.b16 {%0,%1,%2,%3}, [%4];"
                 : "=r"(r0), "=r"(r1), "=r"(r2), "=r"(r3) : "r"(a));
}
__device__ __forceinline__ void mma_f16(unsigned& d0, unsigned& d1,
                                        unsigned a0, unsigned a1, unsigned a2,
                                        unsigned a3, unsigned b0, unsigned b1) {
    asm volatile(
        "mma.sync.aligned.m16n8k16.row.col.f16.f16.f16.f16 "
        "{%0,%1},{%2,%3,%4,%5},{%6,%7},{%0,%1};"
        : "+r"(d0), "+r"(d1)
        : "r"(a0), "r"(a1), "r"(a2), "r"(a3), "r"(b0), "r"(b1));
}
__device__ __forceinline__ void mma_f32(float& c0, float& c1, float& c2, float& c3,
                                        unsigned a0, unsigned a1, unsigned a2,
                                        unsigned a3, unsigned b0, unsigned b1) {
    asm volatile(
        "mma.sync.aligned.m16n8k16.row.col.f32.f16.f16.f32 "
        "{%0,%1,%2,%3},{%4,%5,%6,%7},{%8,%9},{%0,%1,%2,%3};"
        : "+f"(c0), "+f"(c1), "+f"(c2), "+f"(c3)
        : "r"(a0), "r"(a1), "r"(a2), "r"(a3), "r"(b0), "r"(b1));
}

// ---------------------------------------------------------------------------
// fused fp32 -> fp16 converter over three arrays (sizes multiple of 8)
// ---------------------------------------------------------------------------
__global__ void cvt_all(const float* __restrict__ x,   __half* __restrict__ xo, size_t nx,
                        const float* __restrict__ w1,  __half* __restrict__ w1o, size_t n1,
                        const float* __restrict__ w2,  __half* __restrict__ w2o, size_t n2)
{
    size_t i = ((size_t)blockIdx.x * blockDim.x + threadIdx.x) * 8;
    const float* in; __half* out; size_t off;
    if (i < nx) { in = x; out = xo; off = i; }
    else if (i < nx + n1) { in = w1; out = w1o; off = i - nx; }
    else if (i < nx + n1 + n2) { in = w2; out = w2o; off = i - nx - n1; }
    else return;
    float4 a = *(const float4*)(in + off);
    float4 b = *(const float4*)(in + off + 4);
    __half2 h0 = __floats2half2_rn(a.x, a.y);
    __half2 h1 = __floats2half2_rn(a.z, a.w);
    __half2 h2 = __floats2half2_rn(b.x, b.y);
    __half2 h3 = __floats2half2_rn(b.z, b.w);
    uint4 pack;
    pack.x = *(unsigned*)&h0; pack.y = *(unsigned*)&h1;
    pack.z = *(unsigned*)&h2; pack.w = *(unsigned*)&h3;
    *(uint4*)(out + off) = pack;
}

// ===========================================================================
// Raw-mma fp16 GEMM (NT), 4-stage cp.async pipeline at BK=32:
// BM=128, BN=128, 8 warps, warp tile 32x64 (2 m16 x 8 n8).
// wait_group(2) keeps two prefetches in flight; one sync per iteration.
// EPI=0: fp32 store. EPI=1: register RoPE epilogue.
// ===========================================================================
#define LDR 40
#define STAGE_HALF (128 * LDR)
#define NSTAGE 4
#define GEMM_SMEM_R (NSTAGE * 2 * STAGE_HALF * 2)   // 81920 B

template <int EPI>
__global__ void __launch_bounds__(256) gemm_r(
    const __half* __restrict__ A, const __half* __restrict__ Bw,
    float* __restrict__ Cc,
    const float* __restrict__ cosb, const float* __restrict__ sinb,
    __half* __restrict__ qo, __half* __restrict__ ko, __half* __restrict__ vo,
    int M, int N, int K)
{
    extern __shared__ char smem[];
    __half* sS = (__half*)smem;   // [NSTAGE][ A(128xLDR) | B(128xLDR) ]

    const int tid = threadIdx.x;
    const int w   = tid >> 5;
    const int l   = tid & 31;
    const int bm  = blockIdx.y * 128;
    const int bn  = blockIdx.x * 128;
    const int m_off = (w >> 1) * 32;
    const int n_off = (w & 1) * 64;

    const unsigned uS = smem_u32(sS);
    const int lrow16 = (l & 7) + ((l >> 3) & 1) * 8;
    const int lcol8  = (l >> 4) * 8;
    const int g   = l >> 2;
    const int t4  = l & 3;

    float c[2][8][4];
    #pragma unroll
    for (int i = 0; i < 2; i++)
        #pragma unroll
        for (int j = 0; j < 8; j++)
            #pragma unroll
            for (int e = 0; e < 4; e++) c[i][j][e] = 0.0f;

    auto load_stage = [&](int k0, int st) {
        __half* dA = sS + st * 2 * STAGE_HALF;
        __half* dB = dA + STAGE_HALF;
        // 128 rows x 32 halves = 512 chunks of 8 -> 2 per thread, each array
        #pragma unroll
        for (int p = 0; p < 2; p++) {
            int cidx = p * 256 + tid;
            int r = cidx >> 2, c8 = (cidx & 3) * 8;
            cp_async16(&dA[r * LDR + c8], &A[(size_t)(bm + r) * K + k0 + c8]);
        }
        #pragma unroll
        for (int p = 0; p < 2; p++) {
            int cidx = p * 256 + tid;
            int r = cidx >> 2, c8 = (cidx & 3) * 8;
            cp_async16(&dB[r * LDR + c8], &Bw[(size_t)(bn + r) * K + k0 + c8]);
        }
        cp_commit();
    };

    const int nk = K / 32;            // 12
    load_stage(0, 0);
    load_stage(32, 1);
    load_stage(64, 2);

    int st = 0;
    for (int ki = 0; ki < nk; ki++) {
        cp_wait<2>();
        __syncthreads();
        if (ki + 3 < nk) load_stage((ki + 3) * 32, (ki + 3) & 3);

        const unsigned baseA = uS + (unsigned)(st * 2 * STAGE_HALF * 2);
        const unsigned baseB = baseA + (unsigned)(STAGE_HALF * 2);
        st = (st + 1) & 3;

        unsigned bB[8][4];
        #pragma unroll
        for (int j = 0; j < 8; j++) {
            unsigned addr = baseB +
                (unsigned)(((n_off + 8 * j + (l & 7)) * LDR + (l >> 3) * 8) * 2);
            ldsm_x4(bB[j][0], bB[j][1], bB[j][2], bB[j][3], addr);
        }
        #pragma unroll
        for (int kc = 0; kc < 2; kc++) {
            unsigned aA[2][4];
            #pragma unroll
            for (int i = 0; i < 2; i++) {
                unsigned addr = baseA +
                    (unsigned)(((m_off + 16 * i + lrow16) * LDR +
                                kc * 16 + lcol8) * 2);
                ldsm_x4(aA[i][0], aA[i][1], aA[i][2], aA[i][3], addr);
            }
            #pragma unroll
            for (int i = 0; i < 2; i++)
                #pragma unroll
                for (int j = 0; j < 8; j++)
                    mma_f32(c[i][j][0], c[i][j][1], c[i][j][2], c[i][j][3],
                            aA[i][0], aA[i][1], aA[i][2], aA[i][3],
                            bB[j][2 * kc], bB[j][2 * kc + 1]);
        }
    }

    if (EPI == 0) {
        #pragma unroll
        for (int i = 0; i < 2; i++) {
            size_t row_lo = (size_t)(bm + m_off + 16 * i + g);
            size_t row_hi = row_lo + 8;
            float* plo = Cc + row_lo * N + bn + n_off + 2 * t4;
            float* phi = Cc + row_hi * N + bn + n_off + 2 * t4;
            #pragma unroll
            for (int j = 0; j < 8; j++) {
                *(float2*)(plo + 8 * j) = make_float2(c[i][j][0], c[i][j][1]);
                *(float2*)(phi + 8 * j) = make_float2(c[i][j][2], c[i][j][3]);
            }
        }
    } else {
        const int gidx = 2 * blockIdx.x + (w & 1);   // 0..17
        const int i3 = gidx / NH_;
        const int hh = gidx - NH_ * i3;
        const float sc = (i3 == 0) ? 0.125f : 1.0f;
        __half* dst0 = (i3 == 0 ? qo : (i3 == 1 ? ko : vo));
        const int d0 = 2 * t4;

        #pragma unroll
        for (int i = 0; i < 2; i++) {
            #pragma unroll
            for (int rh = 0; rh < 2; rh++) {
                int gm = bm + m_off + 16 * i + g + 8 * rh;
                int b  = gm >> 9, t = gm & 511;
                int e0 = 2 * rh, e1 = 2 * rh + 1;
                float v[8][2];
                #pragma unroll
                for (int j = 0; j < 8; j++) {
                    v[j][0] = c[i][j][e0];
                    v[j][1] = c[i][j][e1];
                }
                if (i3 < 2) {
                    float cs0 = cosb[t * 8 + d0], cs1 = cosb[t * 8 + d0 + 1];
                    float sn0 = sinb[t * 8 + d0], sn1 = sinb[t * 8 + d0 + 1];
                    float r00 = v[0][0] * cs0 - v[1][0] * sn0;
                    float r01 = v[0][1] * cs1 - v[1][1] * sn1;
                    float r10 = v[1][0] * cs0 + v[0][0] * sn0;
                    float r11 = v[1][1] * cs1 + v[0][1] * sn1;
                    v[0][0] = r00; v[0][1] = r01;
                    v[1][0] = r10; v[1][1] = r11;
                }
                __half* dst = dst0 + (((size_t)b * NH_ + hh) * T_ + t) * HD_ + d0;
                #pragma unroll
                for (int j = 0; j < 8; j++) {
                    __half2 h = __floats2half2_rn(v[j][0] * sc, v[j][1] * sc);
                    *(__half2*)(dst + 8 * j) = h;
                }
            }
        }
    }
}

// ===========================================================================
// Attention v6 (R11/R12, unchanged): FA2-style register-resident P.
// ===========================================================================
#define AQ_BYTES  (128 * 72 * 2)
#define AKV_HALF  (64 * 72)
#define ATTN_SMEM (AQ_BYTES + 4 * AKV_HALF * 2)   // 55296

__global__ void __launch_bounds__(256, 2) attn_kernel(
    const __half* __restrict__ q, const __half* __restrict__ k,
    const __half* __restrict__ v, __half* __restrict__ o)
{
    extern __shared__ char smem[];
    __half* sQp = (__half*)smem;
    __half* sKp = (__half*)(smem + AQ_BYTES);
    __half* sVp = (__half*)(smem + AQ_BYTES + 2 * AKV_HALF * 2);

    const int qt = blockIdx.x;
    const int h  = blockIdx.y, b = blockIdx.z;
    const int tid = threadIdx.x, w = tid >> 5, l = tid & 31;
    const int nkt = 2 * (qt + 1);

    const __half* qbase = q + (((size_t)b * NH_ + h) * T_ + qt * 128) * HD_;
    const __half* kbase = k + (((size_t)b * NH_ + h) * T_) * HD_;
    const __half* vbase = v + (((size_t)b * NH_ + h) * T_) * HD_;

    #pragma unroll
    for (int p = 0; p < 4; p++) {
        int idx = p * 256 + tid;
        int r = idx >> 3, c8 = (idx & 7) * 8;
        cp_async16(&sQp[r * 72 + c8], &qbase[r * 64 + c8]);
    }
    #pragma unroll
    for (int p = 0; p < 2; p++) {
        int idx = p * 256 + tid;
        int r = idx >> 3, c8 = (idx & 7) * 8;
        cp_async16(&sKp[r * 72 + c8], &kbase[r * 64 + c8]);
        cp_async16(&sVp[r * 72 + c8], &vbase[r * 64 + c8]);
    }
    cp_commit();
    cp_wait<0>();
    __syncthreads();

    const unsigned uQ = smem_u32(sQp);
    const unsigned uK = smem_u32(sKp);
    const unsigned uV = smem_u32(sVp);

    const int qrow0 = w * 16;
    const int lrow  = (l & 7) + ((l >> 3) & 1) * 8;
    const int lcol8 = (l >> 4) * 8;
    const int g  = l >> 2;
    const int t4 = l & 3;

    unsigned aQ[4][4];
    #pragma unroll
    for (int kk = 0; kk < 4; kk++) {
        unsigned addr = uQ + (unsigned)(((qrow0 + lrow) * 72 + kk * 16 + lcol8) * 2);
        ldsm_x4(aQ[kk][0], aQ[kk][1], aQ[kk][2], aQ[kk][3], addr);
    }

    float oacc[8][4];
    #pragma unroll
    for (int j = 0; j < 8; j++)
        #pragma unroll
        for (int e = 0; e < 4; e++) oacc[j][e] = 0.0f;
    float rs_lo = 0.0f, rs_hi = 0.0f;

    const int qw_base = qt * 128 + qrow0;
    const int grow_lo = qw_base + g;
    const int grow_hi = grow_lo + 8;

    for (int kt = 0; kt < nkt; kt++) {
        const unsigned curK = uK + (unsigned)((kt & 1) * AKV_HALF * 2);
        const unsigned curV = uV + (unsigned)((kt & 1) * AKV_HALF * 2);

        if (kt + 1 < nkt) {
            const __half* kn = kbase + (size_t)(kt + 1) * 64 * 64;
            const __half* vn = vbase + (size_t)(kt + 1) * 64 * 64;
            __half* dK = sKp + ((kt + 1) & 1) * AKV_HALF;
            __half* dV = sVp + ((kt + 1) & 1) * AKV_HALF;
            #pragma unroll
            for (int p = 0; p < 2; p++) {
                int idx = p * 256 + tid;
                int r = idx >> 3, c8 = (idx & 7) * 8;
                cp_async16(&dK[r * 72 + c8], &kn[r * 64 + c8]);
                cp_async16(&dV[r * 72 + c8], &vn[r * 64 + c8]);
            }
            cp_commit();
        }

        const bool active = (64 * kt <= qw_base + 15);
        if (active) {
            const bool maskt = (64 * kt + 63 > qw_base);
            unsigned P[8][2];

            #pragma unroll
            for (int j = 0; j < 8; j++) {
                unsigned d0 = 0, d1 = 0;
                #pragma unroll
                for (int kp = 0; kp < 2; kp++) {
                    unsigned b0, b1, b2, b3;
                    unsigned addr = curK +
                        (unsigned)(((8 * j + (l & 7)) * 72 + kp * 32 + (l >> 3) * 8) * 2);
                    ldsm_x4(b0, b1, b2, b3, addr);
                    mma_f16(d0, d1, aQ[2 * kp][0], aQ[2 * kp][1],
                            aQ[2 * kp][2], aQ[2 * kp][3], b0, b1);
                    mma_f16(d0, d1, aQ[2 * kp + 1][0], aQ[2 * kp + 1][1],
                            aQ[2 * kp + 1][2], aQ[2 * kp + 1][3], b2, b3);
                }
                float2 f0 = __half22float2(*(__half2*)&d0);
                float2 f1 = __half22float2(*(__half2*)&d1);
                float e00 = __expf(f0.x), e01 = __expf(f0.y);
                float e10 = __expf(f1.x), e11 = __expf(f1.y);
                if (maskt) {
                    int c0 = kt * 64 + 8 * j + 2 * t4;
                    if (c0     > grow_lo) e00 = 0.0f;
                    if (c0 + 1 > grow_lo) e01 = 0.0f;
                    if (c0     > grow_hi) e10 = 0.0f;
                    if (c0 + 1 > grow_hi) e11 = 0.0f;
                }
                rs_lo += e00 + e01;
                rs_hi += e10 + e11;
                __half2 p0 = __floats2half2_rn(e00, e01);
                __half2 p1 = __floats2half2_rn(e10, e11);
                P[j][0] = *(unsigned*)&p0;
                P[j][1] = *(unsigned*)&p1;
            }

            #pragma unroll
            for (int kk = 0; kk < 4; kk++) {
                unsigned pa0 = P[2 * kk][0],     pa1 = P[2 * kk][1];
                unsigned pa2 = P[2 * kk + 1][0], pa3 = P[2 * kk + 1][1];
                #pragma unroll
                for (int j2 = 0; j2 < 4; j2++) {
                    unsigned m0, m1, m2, m3;
                    unsigned addr = curV +
                        (unsigned)(((16 * kk + lrow) * 72 + j2 * 16 + lcol8) * 2);
                    ldsm_x4_t(m0, m1, m2, m3, addr);
                    mma_f32(oacc[2 * j2][0], oacc[2 * j2][1],
                            oacc[2 * j2][2], oacc[2 * j2][3],
                            pa0, pa1, pa2, pa3, m0, m1);
                    mma_f32(oacc[2 * j2 + 1][0], oacc[2 * j2 + 1][1],
                            oacc[2 * j2 + 1][2], oacc[2 * j2 + 1][3],
                            pa0, pa1, pa2, pa3, m2, m3);
                }
            }
        }

        cp_wait<0>();
        __syncthreads();
    }

    rs_lo += __shfl_xor_sync(0xffffffffu, rs_lo, 1);
    rs_lo += __shfl_xor_sync(0xffffffffu, rs_lo, 2);
    rs_hi += __shfl_xor_sync(0xffffffffu, rs_hi, 1);
    rs_hi += __shfl_xor_sync(0xffffffffu, rs_hi, 2);
    const float inv_lo = 1.0f / rs_lo;
    const float inv_hi = 1.0f / rs_hi;

    const size_t row_lo = (size_t)b * T_ + qt * 128 + qrow0 + g;
    const size_t row_hi = row_lo + 8;
    __half* obase_lo = o + row_lo * C_ + h * HD_;
    __half* obase_hi = o + row_hi * C_ + h * HD_;
    #pragma unroll
    for (int j = 0; j < 8; j++) {
        int col = 8 * j + 2 * t4;
        __half2 lo = __floats2half2_rn(oacc[j][0] * inv_lo, oacc[j][1] * inv_lo);
        __half2 hi = __floats2half2_rn(oacc[j][2] * inv_hi, oacc[j][3] * inv_hi);
        *(__half2*)(obase_lo + col) = lo;
        *(__half2*)(obase_hi + col) = hi;
    }
}

// ---------------------------------------------------------------------------
extern "C" void kernel_launch(void* const* d_in, const int* in_sizes, int n_in,
                              void* d_out, int out_size)
{
    const float* x    = (const float*)d_in[0];
    const float* Wqkv = (const float*)d_in[1];
    const float* Wout = (const float*)d_in[2];
    const float* cosb = (const float*)d_in[3];
    const float* sinb = (const float*)d_in[4];
    float* out = (float*)d_out;

    __half *xh, *wqkvh, *wouth, *qh, *kh, *vh, *oh;
    cudaGetSymbolAddress((void**)&xh,    g_xh);
    cudaGetSymbolAddress((void**)&wqkvh, g_wqkvh);
    cudaGetSymbolAddress((void**)&wouth, g_wouth);
    cudaGetSymbolAddress((void**)&qh,    g_qh);
    cudaGetSymbolAddress((void**)&kh,    g_kh);
    cudaGetSymbolAddress((void**)&vh,    g_vh);
    cudaGetSymbolAddress((void**)&oh,    g_oh);

    const int M = B_ * T_;

    cudaFuncSetAttribute(gemm_r<0>,
                         cudaFuncAttributeMaxDynamicSharedMemorySize, GEMM_SMEM_R);
    cudaFuncSetAttribute(gemm_r<1>,
                         cudaFuncAttributeMaxDynamicSharedMemorySize, GEMM_SMEM_R);
    cudaFuncSetAttribute(attn_kernel,
                         cudaFuncAttributeMaxDynamicSharedMemorySize, ATTN_SMEM);

    // fused converts
    {
        size_t nx = (size_t)B_ * T_ * C_;
        size_t n1 = (size_t)3 * C_ * C_;
        size_t n2 = (size_t)C_ * C_;
        size_t total8 = (nx + n1 + n2) / 8;
        int blocks = (int)((total8 + 255) / 256);
        cvt_all<<<blocks, 256>>>(x, xh, nx, Wqkv, wqkvh, n1, Wout, wouth, n2);
    }

    // K1: qkv GEMM (raw mma, 4-stage BK=32 pipeline) + register RoPE epilogue
    {
        dim3 grid((3 * C_) / 128, M / 128);
        gemm_r<1><<<grid, 256, GEMM_SMEM_R>>>(
            xh, wqkvh, nullptr, cosb, sinb, qh, kh, vh, M, 3 * C_, C_);
    }
    // K2: causal attention (FA2-style)
    {
        dim3 grid(T_ / 128, NH_, B_);
        attn_kernel<<<grid, 256, ATTN_SMEM>>>(qh, kh, vh, oh);
    }
    // K3: out = o @ Wout^T
    {
        dim3 grid(C_ / 128, M / 128);
        gemm_r<0><<<grid, 256, GEMM_SMEM_R>>>(
            oh, wouth, out, nullptr, nullptr, nullptr, nullptr, nullptr,
            M, C_, C_);
    }
}